// round 11
// baseline (speedup 1.0000x reference)
#include <cuda_runtime.h>
#include <cstdint>
#include <cstddef>

#define B_   128
#define C_   2048
#define HW_  196
#define ND_  32
#define NA_  1845

#define THREADS 128         // 4 warps (R6 proven shape)
#define CK      256         // floats per k-chunk (1KB per W row)
#define NCHUNK  8           // 2048 / 256
#define ATILE   32          // answer rows per block
#define NZ      4           // sample-group split across blockIdx.x

// Scratch for attended features (cudaMalloc is forbidden) — 1 MB, L2-hot.
__device__ __align__(1024) float g_att[B_ * C_];

// ---- dynamic smem layout (bytes) ----
// W bufs 2x32KB at 0; control block after.
#define SM_LIST  65536                    // int[128] compacted sample list
#define SM_MATCH (SM_LIST + 512)          // int[128] match flags
#define SM_CNT   (SM_MATCH + 512)
#define SM_IS64  (SM_CNT + 4)
#define SM_TOT   (SM_IS64 + 4)            // ~65KB -> 3 blocks/SM

// ---------------------------------------------------------------------------
// Kernel 1: attended[b][c] = (1/196) * sum_hw mask[b][hw] * features[b][c][hw]
// One warp per (b,c) row; ~78% of HBM peak — unchanged.
// ---------------------------------------------------------------------------
__global__ void __launch_bounds__(256) k_attend(const float* __restrict__ mask,
                                                const float* __restrict__ feat)
{
    int gw   = (blockIdx.x * 256 + threadIdx.x) >> 5;
    int lane = threadIdx.x & 31;
    if (gw >= B_ * C_) return;
    int b = gw >> 11;

    const float4* f  = (const float4*)(feat + (size_t)gw * HW_);
    const float4* mk = (const float4*)(mask + (size_t)b  * HW_);

    float4 a0 = f[lane], m0 = mk[lane];
    float s = a0.x * m0.x + a0.y * m0.y + a0.z * m0.z + a0.w * m0.w;
    if (lane < 17) {
        float4 a1 = f[lane + 32], m1 = mk[lane + 32];
        s += a1.x * m1.x + a1.y * m1.y + a1.z * m1.z + a1.w * m1.w;
    }
    #pragma unroll
    for (int o = 16; o; o >>= 1) s += __shfl_xor_sync(0xffffffffu, s, o);
    if (lane == 0) g_att[gw] = s * (1.0f / 196.0f);
}

// ---------------------------------------------------------------------------
// Helpers
// ---------------------------------------------------------------------------
__device__ __forceinline__ void fma2(unsigned long long& d,
                                     unsigned long long a,
                                     unsigned long long b)
{
    asm("fma.rn.f32x2 %0, %1, %2, %0;" : "+l"(d) : "l"(a), "l"(b));
}

__device__ __forceinline__ uint32_t smem_u32(const void* p) {
    uint32_t a;
    asm("{ .reg .u64 t; cvta.to.shared.u64 t, %1; cvt.u32.u64 %0, t; }"
        : "=r"(a) : "l"(p));
    return a;
}

__device__ __forceinline__ void cp16(uint32_t saddr, const void* gaddr) {
    asm volatile("cp.async.cg.shared.global [%0], [%1], 16;"
                 :: "r"(saddr), "l"(gaddr));
}
__device__ __forceinline__ void cp_commit() {
    asm volatile("cp.async.commit_group;");
}
template <int N>
__device__ __forceinline__ void cp_wait() {
    asm volatile("cp.async.wait_group %0;" :: "n"(N));
}

// ---------------------------------------------------------------------------
// Stage one W k-chunk: 32 rows x CK floats (32KB). 128 thr x 16 cp16.
// ---------------------------------------------------------------------------
__device__ __forceinline__ void issueW(uint32_t smb,
                                       const float* __restrict__ Wg,
                                       int k0, int buf, int tid)
{
    uint32_t wdst = smb + buf * 32768;
    #pragma unroll
    for (int i = 0; i < 16; i++) {
        int idx = i * 128 + tid;
        int row = idx >> 6, col = idx & 63;
        cp16(wdst + idx * 16, Wg + (size_t)row * C_ + k0 + col * 4);
    }
    cp_commit();
}

// ---------------------------------------------------------------------------
// One pass: 32 W rows x 4 samples, NBUF=2 cp.async pipeline (R6 shape).
// X comes straight from L2 via LDG (g_att is 1MB, resident, 58x reused).
// ---------------------------------------------------------------------------
__device__ __forceinline__ void run_pass(uint32_t smb, char* sm,
                                         const float* __restrict__ Wg,
                                         int tid, int lane, int warp,
                                         const int* bj,
                                         int a0c, int a0nom, int d,
                                         const float* __restrict__ bias,
                                         float* __restrict__ out)
{
    const ulonglong2* xp[4];
    #pragma unroll
    for (int j = 0; j < 4; j++)
        xp[j] = (const ulonglong2*)(g_att + (size_t)bj[j] * C_);

    unsigned long long acc[8][4];
    #pragma unroll
    for (int r = 0; r < 8; r++)
        #pragma unroll
        for (int j = 0; j < 4; j++) acc[r][j] = 0ull;

    issueW(smb, Wg, 0, 0, tid);

    for (int k = 0; k < NCHUNK; k++) {
        int buf = k & 1;
        if (k + 1 < NCHUNK) {
            // buf (k+1)&1 last read at stage k-1; trailing barrier passed.
            issueW(smb, Wg, (k + 1) * CK, (k + 1) & 1, tid);
            cp_wait<1>();
        } else {
            cp_wait<0>();
        }
        __syncthreads();                               // stage k visible

        const float* Wb = (const float*)(sm + buf * 32768);
        int cbase = k * (CK / 4);                      // float4 index into X
        #pragma unroll
        for (int st = 0; st < 2; st++) {               // CK/4 = 64 float4
            int c = lane + st * 32;
            ulonglong2 w[8];
            #pragma unroll
            for (int r = 0; r < 8; r++)
                w[r] = ((const ulonglong2*)(Wb + (warp * 8 + r) * CK))[c];
            #pragma unroll
            for (int j = 0; j < 4; j++) {
                ulonglong2 x = xp[j][cbase + c];       // L2 hit
                #pragma unroll
                for (int r = 0; r < 8; r++) {
                    fma2(acc[r][j], w[r].x, x.x);
                    fma2(acc[r][j], w[r].y, x.y);
                }
            }
        }
        __syncthreads();                               // WAR on buf
    }

    #pragma unroll
    for (int r = 0; r < 8; r++) {
        int a = a0c + warp * 8 + r;
        #pragma unroll
        for (int j = 0; j < 4; j++) {                  // padded j idempotent
            float v = __uint_as_float((unsigned)(acc[r][j] & 0xffffffffu))
                    + __uint_as_float((unsigned)(acc[r][j] >> 32));
            #pragma unroll
            for (int o = 16; o; o >>= 1) v += __shfl_xor_sync(0xffffffffu, v, o);
            if (lane == 0 && a >= a0nom)
                out[(size_t)bj[j] * NA_ + a] = v + bias[(size_t)d * NA_ + a];
        }
    }
}

// ---------------------------------------------------------------------------
// Kernel 2: grouped GEMM. Grid (NZ, 58, 32): x = sample group (z-split so
// same-(tile,d) siblings are wave-adjacent and share W through L2),
// y = answer tile, z = descriptor.
// s_list is built DETERMINISTICALLY (ascending sample index) so sibling
// blocks agree on the group partition (R10 bug: atomicAdd order differed).
// ---------------------------------------------------------------------------
__global__ void __launch_bounds__(THREADS, 3) k_gemm(const void* __restrict__ inst_raw,
                                                     const float* __restrict__ W,
                                                     const float* __restrict__ bias,
                                                     float* __restrict__ out)
{
    extern __shared__ char sm[];
    uint32_t smb = smem_u32(sm);
    int* s_list  = (int*)(sm + SM_LIST);
    int* s_match = (int*)(sm + SM_MATCH);
    int* s_cnt   = (int*)(sm + SM_CNT);
    int* s_is64  = (int*)(sm + SM_IS64);

    if (threadIdx.x == 0) {
        // Detect int64 vs int32 instance layout (values 0..31 => odd words 0).
        const unsigned* pw = (const unsigned*)inst_raw;
        unsigned orv = 0;
        for (int i = 1; i < 128; i += 2) orv |= pw[i];
        *s_is64 = (orv == 0) ? 1 : 0;
    }
    __syncthreads();

    int d = blockIdx.z;
    {   // 128 threads write match flags (deterministic by construction)
        int v = *s_is64 ? (int)((const long long*)inst_raw)[threadIdx.x]
                        : ((const int*)inst_raw)[threadIdx.x];
        s_match[threadIdx.x] = (v == d) ? 1 : 0;
    }
    __syncthreads();
    if (threadIdx.x == 0) {                            // serial compaction:
        int c = 0;                                     // ascending order, same
        for (int i = 0; i < B_; i++)                   // in every sibling block
            if (s_match[i]) s_list[c++] = i;
        *s_cnt = c;
    }
    __syncthreads();

    int m = *s_cnt;
    if (m == 0) return;                                // unused descriptor

    int tid  = threadIdx.x;
    int lane = tid & 31;
    int warp = tid >> 5;
    int a0nom = blockIdx.y * ATILE;
    int a0c   = a0nom > NA_ - ATILE ? NA_ - ATILE : a0nom;
    const float* W0 = W + ((size_t)d * NA_ + a0c) * C_;

    // This block handles sample groups z, z+NZ, z+2NZ, ... (usually just one).
    for (int mbase = blockIdx.x * 4; mbase < m; mbase += 4 * NZ) {
        int mc = m - mbase; if (mc > 4) mc = 4;
        int bj[4];                                     // registers only (R3)
        #pragma unroll
        for (int j = 0; j < 4; j++)
            bj[j] = s_list[mbase + (j < mc ? j : mc - 1)];

        run_pass(smb, sm, W0, tid, lane, warp, bj, a0c, a0nom, d, bias, out);
    }
}

// ---------------------------------------------------------------------------
// Inputs (metadata order): mask f32[128,1,14,14], features f32[128,2048,14,14],
// instance int[128], W f32[32,1845,2048], b f32[32,1845]. Output f32[128,1845].
// ---------------------------------------------------------------------------
extern "C" void kernel_launch(void* const* d_in, const int* in_sizes, int n_in,
                              void* d_out, int out_size)
{
    const float* mask = (const float*)d_in[0];
    const float* feat = (const float*)d_in[1];
    const void*  inst = d_in[2];
    const float* W    = (const float*)d_in[3];
    const float* bias = (const float*)d_in[4];
    float* out = (float*)d_out;

    int blocks1 = (B_ * C_) / 8;                       // warp per (b,c) row
    k_attend<<<blocks1, 256>>>(mask, feat);

    cudaFuncSetAttribute(k_gemm, cudaFuncAttributeMaxDynamicSharedMemorySize,
                         SM_TOT);
    dim3 g2(NZ, (NA_ + ATILE - 1) / ATILE, ND_);       // (4, 58, 32)
    k_gemm<<<g2, THREADS, SM_TOT>>>(inst, W, bias, out);
}

// round 12
// speedup vs baseline: 1.3658x; 1.3658x over previous
#include <cuda_runtime.h>
#include <cstdint>
#include <cstddef>

#define B_   128
#define C_   2048
#define HW_  196
#define ND_  32
#define NA_  1845

#define THREADS 128         // 4 warps
#define CK      128         // floats per k-chunk (512B per W row)
#define ATILE   32          // answer rows per block

// Scratch for attended features (cudaMalloc is forbidden) — 1 MB.
__device__ __align__(1024) float g_att[B_ * C_];

// ---- dynamic smem layout (bytes) ----
// Path A: W 3x16KB at 0, X 3x2KB at 48KB (ends 54KB).
// Path B: W 3x8KB  at 0, X 3x4KB at 24KB (ends 36KB).
// Control block at 55296.
#define A_XOFF  49152
#define B_XOFF  24576
#define SM_CTRL 55296
#define SM_LIST SM_CTRL                   // int[128]
#define SM_BJ   (SM_LIST + 512)           // int[8]
#define SM_CNT  (SM_BJ + 32)
#define SM_IS64 (SM_CNT + 4)
#define SM_TOT  (SM_IS64 + 4)             // ~55.9KB -> 4 blocks/SM

// ---------------------------------------------------------------------------
// Kernel 1: attended[b][c] = (1/196) * sum_hw mask[b][hw] * features[b][c][hw]
// One warp per (b,c) row; ~78% of HBM peak — unchanged.
// ---------------------------------------------------------------------------
__global__ void __launch_bounds__(256) k_attend(const float* __restrict__ mask,
                                                const float* __restrict__ feat)
{
    int gw   = (blockIdx.x * 256 + threadIdx.x) >> 5;
    int lane = threadIdx.x & 31;
    if (gw >= B_ * C_) return;
    int b = gw >> 11;

    const float4* f  = (const float4*)(feat + (size_t)gw * HW_);
    const float4* mk = (const float4*)(mask + (size_t)b  * HW_);

    float4 a0 = f[lane], m0 = mk[lane];
    float s = a0.x * m0.x + a0.y * m0.y + a0.z * m0.z + a0.w * m0.w;
    if (lane < 17) {
        float4 a1 = f[lane + 32], m1 = mk[lane + 32];
        s += a1.x * m1.x + a1.y * m1.y + a1.z * m1.z + a1.w * m1.w;
    }
    #pragma unroll
    for (int o = 16; o; o >>= 1) s += __shfl_xor_sync(0xffffffffu, s, o);
    if (lane == 0) g_att[gw] = s * (1.0f / 196.0f);
}

// ---------------------------------------------------------------------------
// Helpers
// ---------------------------------------------------------------------------
__device__ __forceinline__ void fma2(unsigned long long& d,
                                     unsigned long long a,
                                     unsigned long long b)
{
    asm("fma.rn.f32x2 %0, %1, %2, %0;" : "+l"(d) : "l"(a), "l"(b));
}

__device__ __forceinline__ uint32_t smem_u32(const void* p) {
    uint32_t a;
    asm("{ .reg .u64 t; cvta.to.shared.u64 t, %1; cvt.u32.u64 %0, t; }"
        : "=r"(a) : "l"(p));
    return a;
}

__device__ __forceinline__ void cp16(uint32_t saddr, const void* gaddr) {
    asm volatile("cp.async.cg.shared.global [%0], [%1], 16;"
                 :: "r"(saddr), "l"(gaddr));
}
__device__ __forceinline__ void cp_commit() {
    asm volatile("cp.async.commit_group;");
}
template <int N>
__device__ __forceinline__ void cp_wait() {
    asm volatile("cp.async.wait_group %0;" :: "n"(N));
}

// ===========================================================================
// Path A (mc<=4): 16 stages over k. Stage = W 32 rows x 128 f (16KB) +
// X 4 x 128 f (2KB). NBUF=3, single barrier/stage, 2-stage lookahead.
// ===========================================================================
__device__ __forceinline__ void issueA(uint32_t smb, char* sm,
                                       const float* __restrict__ Wg,
                                       int s, int tid)
{
    int k0 = s * CK, buf = s % 3;
    uint32_t wdst = smb + buf * 16384;
    #pragma unroll
    for (int i = 0; i < 8; i++) {                      // 1024 f4 / 128 thr
        int idx = i * 128 + tid;
        int row = idx >> 5, col = idx & 31;
        cp16(wdst + idx * 16, Wg + (size_t)row * C_ + k0 + col * 4);
    }
    const int* bjs = (const int*)(sm + SM_BJ);
    int j = tid >> 5, col = tid & 31;                  // 128 f4, 1/thread
    cp16(smb + A_XOFF + buf * 2048 + tid * 16,
         g_att + (size_t)bjs[j] * C_ + k0 + col * 4);
    cp_commit();
}

__device__ __forceinline__ void runA(uint32_t smb, char* sm,
                                     const float* __restrict__ Wg,
                                     int tid, int lane, int warp,
                                     const int* bj,
                                     int a0c, int a0nom, int d,
                                     const float* __restrict__ bias,
                                     float* __restrict__ out)
{
    unsigned long long acc[8][4];
    #pragma unroll
    for (int r = 0; r < 8; r++)
        #pragma unroll
        for (int j = 0; j < 4; j++) acc[r][j] = 0ull;

    issueA(smb, sm, Wg, 0, tid);
    issueA(smb, sm, Wg, 1, tid);

    for (int s = 0; s < 16; s++) {
        if (s + 1 < 16) cp_wait<1>(); else cp_wait<0>();
        __syncthreads();                               // stage s visible; WAR ok
        if (s + 2 < 16) issueA(smb, sm, Wg, s + 2, tid);

        const float* Wb = (const float*)(sm + (s % 3) * 16384);
        const float* Xb = (const float*)(sm + A_XOFF + (s % 3) * 2048);
        // CK/4 = 32 float4 = exactly one lane-step
        ulonglong2 w[8];
        #pragma unroll
        for (int r = 0; r < 8; r++)
            w[r] = ((const ulonglong2*)(Wb + (warp * 8 + r) * CK))[lane];
        #pragma unroll
        for (int j = 0; j < 4; j++) {
            ulonglong2 x = ((const ulonglong2*)(Xb + j * CK))[lane];
            #pragma unroll
            for (int r = 0; r < 8; r++) {
                fma2(acc[r][j], w[r].x, x.x);
                fma2(acc[r][j], w[r].y, x.y);
            }
        }
    }

    #pragma unroll
    for (int r = 0; r < 8; r++) {
        int a = a0c + warp * 8 + r;
        #pragma unroll
        for (int j = 0; j < 4; j++) {                  // padded j idempotent
            float v = __uint_as_float((unsigned)(acc[r][j] & 0xffffffffu))
                    + __uint_as_float((unsigned)(acc[r][j] >> 32));
            #pragma unroll
            for (int o = 16; o; o >>= 1) v += __shfl_xor_sync(0xffffffffu, v, o);
            if (lane == 0 && a >= a0nom)
                out[(size_t)bj[j] * NA_ + a] = v + bias[(size_t)d * NA_ + a];
        }
    }
}

// ===========================================================================
// Path B (5<=mc<=8): 32 flattened stages (h,k); h = 16-row sub-tile (2 of
// them), k = 16 chunks. Stage = W 16 x 128 f (8KB) + X 8 x 128 f (4KB).
// NBUF=3, single barrier/stage, 2-stage lookahead. W streamed exactly once.
// ===========================================================================
__device__ __forceinline__ void issueB(uint32_t smb, char* sm,
                                       const float* __restrict__ Wg32,
                                       int s, int tid)
{
    int h = s >> 4, k0 = (s & 15) * CK, buf = s % 3;
    const float* Wg = Wg32 + (size_t)(h * 16) * C_;

    uint32_t wdst = smb + buf * 8192;
    #pragma unroll
    for (int i = 0; i < 4; i++) {                      // 512 f4 / 128 thr
        int idx = i * 128 + tid;
        int row = idx >> 5, col = idx & 31;
        cp16(wdst + idx * 16, Wg + (size_t)row * C_ + k0 + col * 4);
    }
    const int* bjs = (const int*)(sm + SM_BJ);
    uint32_t xdst = smb + B_XOFF + buf * 4096;
    #pragma unroll
    for (int i = 0; i < 2; i++) {                      // 256 f4 / 128 thr
        int idx = i * 128 + tid;
        int j = idx >> 5, col = idx & 31;
        cp16(xdst + idx * 16, g_att + (size_t)bjs[j] * C_ + k0 + col * 4);
    }
    cp_commit();
}

__device__ __forceinline__ void runB(uint32_t smb, char* sm,
                                     const float* __restrict__ Wg32,
                                     int tid, int lane, int warp,
                                     const int* bj,
                                     int a0c, int a0nom, int d,
                                     const float* __restrict__ bias,
                                     float* __restrict__ out)
{
    unsigned long long acc[4][8];
    #pragma unroll
    for (int r = 0; r < 4; r++)
        #pragma unroll
        for (int j = 0; j < 8; j++) acc[r][j] = 0ull;

    issueB(smb, sm, Wg32, 0, tid);
    issueB(smb, sm, Wg32, 1, tid);

    for (int s = 0; s < 32; s++) {
        if (s + 1 < 32) cp_wait<1>(); else cp_wait<0>();
        __syncthreads();                               // stage s visible; WAR ok
        if (s + 2 < 32) issueB(smb, sm, Wg32, s + 2, tid);

        const float* Wb = (const float*)(sm + (s % 3) * 8192);
        const float* Xb = (const float*)(sm + B_XOFF + (s % 3) * 4096);
        ulonglong2 w[4];
        #pragma unroll
        for (int r = 0; r < 4; r++)
            w[r] = ((const ulonglong2*)(Wb + (warp * 4 + r) * CK))[lane];
        #pragma unroll
        for (int j = 0; j < 8; j++) {
            ulonglong2 x = ((const ulonglong2*)(Xb + j * CK))[lane];
            #pragma unroll
            for (int r = 0; r < 4; r++) {
                fma2(acc[r][j], w[r].x, x.x);
                fma2(acc[r][j], w[r].y, x.y);
            }
        }

        if ((s & 15) == 15) {                          // end of sub-tile h
            int h = s >> 4;
            #pragma unroll
            for (int r = 0; r < 4; r++) {
                int a = a0c + h * 16 + warp * 4 + r;
                #pragma unroll
                for (int j = 0; j < 8; j++) {          // padded j idempotent
                    float v = __uint_as_float((unsigned)(acc[r][j] & 0xffffffffu))
                            + __uint_as_float((unsigned)(acc[r][j] >> 32));
                    #pragma unroll
                    for (int o = 16; o; o >>= 1)
                        v += __shfl_xor_sync(0xffffffffu, v, o);
                    if (lane == 0 && a >= a0nom)
                        out[(size_t)bj[j] * NA_ + a] =
                            v + bias[(size_t)d * NA_ + a];
                    acc[r][j] = 0ull;
                }
            }
        }
    }
}

// ---------------------------------------------------------------------------
// Kernel 2: grouped GEMM. 4 warps, target 4 blocks/SM. m<=8: W streamed once.
// ---------------------------------------------------------------------------
__global__ void __launch_bounds__(THREADS, 4) k_gemm(const void* __restrict__ inst_raw,
                                                     const float* __restrict__ W,
                                                     const float* __restrict__ bias,
                                                     float* __restrict__ out)
{
    extern __shared__ char sm[];
    uint32_t smb = smem_u32(sm);
    int* s_list = (int*)(sm + SM_LIST);
    int* s_bj   = (int*)(sm + SM_BJ);
    int* s_cnt  = (int*)(sm + SM_CNT);
    int* s_is64 = (int*)(sm + SM_IS64);

    if (threadIdx.x == 0) {
        // Detect int64 vs int32 instance layout (values 0..31 => odd words 0).
        const unsigned* pw = (const unsigned*)inst_raw;
        unsigned orv = 0;
        for (int i = 1; i < 128; i += 2) orv |= pw[i];
        *s_is64 = (orv == 0) ? 1 : 0;
        *s_cnt  = 0;
    }
    __syncthreads();

    int d = blockIdx.y;
    {   // 128 threads scan all 128 instances
        int v = *s_is64 ? (int)((const long long*)inst_raw)[threadIdx.x]
                        : ((const int*)inst_raw)[threadIdx.x];
        if (v == d) {
            int p = atomicAdd(s_cnt, 1);
            s_list[p] = threadIdx.x;
        }
    }
    __syncthreads();

    int m = *s_cnt;
    if (m == 0) return;                                // unused descriptor

    int tid  = threadIdx.x;
    int lane = tid & 31;
    int warp = tid >> 5;
    int a0nom = blockIdx.x * ATILE;
    int a0c   = a0nom > NA_ - ATILE ? NA_ - ATILE : a0nom;
    const float* W0 = W + ((size_t)d * NA_ + a0c) * C_;

    for (int mbase = 0; mbase < m; mbase += 8) {
        int mc = m - mbase; if (mc > 8) mc = 8;
        __syncthreads();                               // prior group's reads done
        if (tid < 8) s_bj[tid] = s_list[mbase + (tid < mc ? tid : mc - 1)];
        __syncthreads();

        int bj[8];                                     // registers only (R3)
        #pragma unroll
        for (int j = 0; j < 8; j++) bj[j] = s_bj[j];

        if (mc <= 4)
            runA(smb, sm, W0, tid, lane, warp, bj, a0c, a0nom, d, bias, out);
        else
            runB(smb, sm, W0, tid, lane, warp, bj, a0c, a0nom, d, bias, out);
    }
}

// ---------------------------------------------------------------------------
// Inputs (metadata order): mask f32[128,1,14,14], features f32[128,2048,14,14],
// instance int[128], W f32[32,1845,2048], b f32[32,1845]. Output f32[128,1845].
// ---------------------------------------------------------------------------
extern "C" void kernel_launch(void* const* d_in, const int* in_sizes, int n_in,
                              void* d_out, int out_size)
{
    const float* mask = (const float*)d_in[0];
    const float* feat = (const float*)d_in[1];
    const void*  inst = d_in[2];
    const float* W    = (const float*)d_in[3];
    const float* bias = (const float*)d_in[4];
    float* out = (float*)d_out;

    int blocks1 = (B_ * C_) / 8;                       // warp per (b,c) row
    k_attend<<<blocks1, 256>>>(mask, feat);

    cudaFuncSetAttribute(k_gemm, cudaFuncAttributeMaxDynamicSharedMemorySize,
                         SM_TOT);
    dim3 g2((NA_ + ATILE - 1) / ATILE, ND_);           // (58, 32)
    k_gemm<<<g2, THREADS, SM_TOT>>>(inst, W, bias, out);
}